// round 13
// baseline (speedup 1.0000x reference)
#include <cuda_runtime.h>
#include <cuda_fp16.h>
#include <math.h>
#include <stdint.h>

#define NH     4096
#define K2     8192
#define GRIDB  128          // blocks (<= 148 SMs -> co-resident, barrier safe)
#define TPB    512          // 16 warps = 2 chains x 8 warps
#define ROWS_PB 32

// ---------------- persistent device scratch (no allocations) ----------------
__device__ __half g_W1p[(size_t)NH * NH];   // fp16 f_W1, fragment-major
__device__ __half g_W2p[(size_t)NH * NH];   // fp16 f_W2, fragment-major
__device__ __half g_v[2][NH];               // per-chain ODE input vector (fp16)
__device__ __half g_u[2][NH];               // per-chain tanh hidden (fp16)
__device__ float  g_vfin[2][NH];            // h after full integration (fp32)
__device__ float  g_g[2][NH];
__device__ float  g_hhat[2][NH];
__device__ float  g_hnew[2][NH];
__device__ float  g_xd[2][NH];
__device__ unsigned g_arrive;               // full-grid barrier (GRU/out)
__device__ unsigned g_ctr[2 * 32];          // per-chain counters (padded lines)

__global__ void k_reset()
{
    if (threadIdx.x == 0) g_arrive = 0u;
    if (threadIdx.x < 64) g_ctr[threadIdx.x] = 0u;
}

// ------- fp32 -> fp16 + permute to mma A-fragment-major layout --------------
__global__ __launch_bounds__(256)
void k_perm(const float* __restrict__ W, __half* __restrict__ P)
{
    const int gidx = blockIdx.x * 256 + threadIdx.x;   // tile*32 + lane
    const int lane = gidx & 31, tile = gidx >> 5;
    const int rg = tile >> 8, kt = tile & 255;
    const int R0 = rg * 16, C0 = kt * 16;
    const int g = lane >> 2, q = lane & 3;
    const float2* r0p = reinterpret_cast<const float2*>(W + (size_t)(R0 + g)     * NH + C0 + 2*q);
    const float2* r8p = reinterpret_cast<const float2*>(W + (size_t)(R0 + 8 + g) * NH + C0 + 2*q);
    float2 a01 = r0p[0];
    float2 a23 = r8p[0];
    float2 a45 = r0p[4];
    float2 a67 = r8p[4];
    __half2 h0 = __floats2half2_rn(a01.x, a01.y);
    __half2 h1 = __floats2half2_rn(a23.x, a23.y);
    __half2 h2 = __floats2half2_rn(a45.x, a45.y);
    __half2 h3 = __floats2half2_rn(a67.x, a67.y);
    uint4 o;
    o.x = *reinterpret_cast<uint32_t*>(&h0);
    o.y = *reinterpret_cast<uint32_t*>(&h1);
    o.z = *reinterpret_cast<uint32_t*>(&h2);
    o.w = *reinterpret_cast<uint32_t*>(&h3);
    reinterpret_cast<uint4*>(P)[gidx] = o;
}

// ---------------- full-grid barrier (GRU/out phases) ----------------
__device__ __forceinline__ void bar_arrive()
{
    __syncthreads();
    if (threadIdx.x == 0) {
        unsigned* p = &g_arrive;
        asm volatile("red.release.gpu.global.add.u32 [%0], 1;" :: "l"(p) : "memory");
    }
}
__device__ __forceinline__ void bar_wait(unsigned& target)
{
    if (threadIdx.x == 0) {
        unsigned* p = &g_arrive;
        unsigned v;
        do {
            asm volatile("ld.acquire.gpu.global.u32 %0, [%1];" : "=r"(v) : "l"(p) : "memory");
        } while (v < target);
    }
    __syncthreads();
    target += GRIDB;
}

// ---------------- per-chain counter ops ----------------
__device__ __forceinline__ void chain_release(unsigned* p)
{
    asm volatile("red.release.gpu.global.add.u32 [%0], 1;" :: "l"(p) : "memory");
}
// lane 0 of one chain warp polls; whole chain synced by named barrier after.
__device__ __forceinline__ void chain_wait(unsigned* p, unsigned tgt, int lane)
{
    if (lane == 0) {
        unsigned v;
        do {
            asm volatile("ld.acquire.gpu.global.u32 %0, [%1];" : "=r"(v) : "l"(p) : "memory");
        } while (v < tgt);
    }
    __syncwarp();
}

__device__ __forceinline__ float tanh_fast(float x)
{
    float y;
    asm("tanh.approx.f32 %0, %1;" : "=f"(y) : "f"(x));
    return y;
}

// ---------------- HMMA m16n8k16 fp32-accum ----------------
__device__ __forceinline__ void mma16816(float c[4], const uint4& a,
                                         uint32_t b0, uint32_t b1)
{
    asm volatile(
        "mma.sync.aligned.m16n8k16.row.col.f32.f16.f16.f32 "
        "{%0,%1,%2,%3}, {%4,%5,%6,%7}, {%8,%9}, {%0,%1,%2,%3};"
        : "+f"(c[0]), "+f"(c[1]), "+f"(c[2]), "+f"(c[3])
        : "r"(a.x), "r"(a.y), "r"(a.z), "r"(a.w), "r"(b0), "r"(b1));
}

// chain warp layout: 8 warps = 2 rg x 4 kc, K=1024 per warp (64 steps)
__device__ __forceinline__ const uint4* a_ptr(const __half* Wp, int rg, int kc, int lane)
{
    const int rg_glob = blockIdx.x * 2 + rg;
    return reinterpret_cast<const uint4*>(Wp)
         + ((size_t)rg_glob * 256 + kc * 64) * 32 + lane;
}

__device__ __forceinline__ void a_prefetch(uint4* abuf, const uint4* A)
{
    #pragma unroll
    for (int p = 0; p < 8; p++) abuf[p] = A[p * 32];
}

// 64-step mma mainloop, N=1 (single batch vector), ring-8 A, B from chain smem.
__device__ __forceinline__ void ode_mma64(uint4* abuf, const uint4* A,
                                          const __half* __restrict__ sB,
                                          float* __restrict__ part,
                                          int rg, int kc, int lane)
{
    const int n = lane >> 2, q = lane & 3;
    const bool hasB = (n == 0);
    const __half* vb = sB + kc * 1024 + q * 2;

    float c0[4] = {0.f,0.f,0.f,0.f}, c1[4] = {0.f,0.f,0.f,0.f};
    #pragma unroll
    for (int s = 0; s < 64; s++) {
        uint4 a = abuf[s & 7];
        if (s < 56) abuf[s & 7] = A[(size_t)(s + 8) * 32];
        uint32_t b0 = 0u, b1 = 0u;
        if (hasB) {
            b0 = *reinterpret_cast<const uint32_t*>(vb + s * 16);
            b1 = *reinterpret_cast<const uint32_t*>(vb + s * 16 + 8);
        }
        if (s & 1) mma16816(c1, a, b0, b1);
        else       mma16816(c0, a, b0, b1);
    }
    if (q == 0) {
        const int r = rg * 16 + n;
        part[kc * 32 + r]     = c0[0] + c1[0];
        part[kc * 32 + r + 8] = c0[2] + c1[2];
    }
}

// ---------------- fp32 warp dots (GRU / out) ----------------
template<int K4>
__device__ __forceinline__ void wdot_f2(const float4* __restrict__ Wr,
                                        const float4* __restrict__ v0,
                                        const float4* __restrict__ v1,
                                        int lane, float& a0, float& a1)
{
    a0 = 0.f; a1 = 0.f;
    #pragma unroll 8
    for (int i = lane; i < K4; i += 32) {
        float4 w = Wr[i], x0 = v0[i], x1 = v1[i];
        a0 += w.x*x0.x + w.y*x0.y + w.z*x0.z + w.w*x0.w;
        a1 += w.x*x1.x + w.y*x1.y + w.z*x1.z + w.w*x1.w;
    }
    #pragma unroll
    for (int off = 16; off; off >>= 1) {
        a0 += __shfl_down_sync(0xffffffffu, a0, off);
        a1 += __shfl_down_sync(0xffffffffu, a1, off);
    }
}

template<int K4>
__device__ __forceinline__ float wdot_f1(const float4* __restrict__ Wr,
                                         const float4* __restrict__ v, int lane)
{
    float a = 0.f;
    #pragma unroll 8
    for (int i = lane; i < K4; i += 32) {
        float4 w = Wr[i], x = v[i];
        a += w.x*x.x + w.y*x.y + w.z*x.z + w.w*x.w;
    }
    #pragma unroll
    for (int off = 16; off; off >>= 1) a += __shfl_down_sync(0xffffffffu, a, off);
    return a;
}

// ---------------- the whole model in one persistent kernel ------------------
__global__ __launch_bounds__(TPB, 1)
void k_all(const float* __restrict__ f_b1, const float* __restrict__ f_b2,
           const float* __restrict__ i2h_W, const float* __restrict__ i2h_b,
           const float* __restrict__ h2o_W, const float* __restrict__ h2o_b,
           const float* __restrict__ x_f, const float* __restrict__ x_b,
           const float* __restrict__ h_f, const float* __restrict__ h_b,
           const float* __restrict__ tf, const float* __restrict__ tb,
           float* __restrict__ out, int nsteps)
{
    __shared__ union {
        struct {
            __half sB[2][NH];              // 16 KB: per-chain B vector
            float  part[2][128];           //  1 KB: per-chain partials (4kc x 32r)
        } ode;
        float svf[2][NH];                  // 32 KB (xdot / GRU / out)
    } sm;
    __shared__ float sdt[2][16];           // per-chain dt table

    const int tid  = threadIdx.x;
    const int warp = tid >> 5, lane = tid & 31;
    const int ch   = warp >> 3;            // chain 0 = batch f, 1 = batch b
    const int cw   = warp & 7;             // warp within chain
    const int rg   = cw >> 2, kc = cw & 3;
    const int ctid = cw * 32 + lane;       // 0..255 within chain
    unsigned target = GRIDB;               // full-barrier target
    uint4 abuf[8];

    const uint4* A1 = a_ptr(g_W1p, rg, kc, lane);
    const uint4* A2 = a_ptr(g_W2p, rg, kc, lane);
    unsigned* ctr = &g_ctr[ch * 32];

    // ---- dt table ----
    if (tid < 15)      sdt[0][tid] = tf[tid + 1] - tf[tid];
    else if (tid < 32 && tid >= 16 && tid - 16 < 15)
                       sdt[1][tid - 16] = tb[tid - 16 + 1] - tb[tid - 16];

    // ---- chain reducer state: warp 0 (chain f) / warp 8 (chain b), lane = row
    const int red_rw = blockIdx.x * ROWS_PB + lane;    // 32 rows per block
    const bool is_red = (cw == 0);
    float hbase = 0.f, ksumr = 0.f, bias1 = 0.f, bias2 = 0.f;
    if (is_red) {
        hbase = (ch ? h_b : h_f)[red_rw];
        bias1 = f_b1[red_rw];
        bias2 = f_b2[red_rw];
    }

    // ---- GRU x-half dot (all 16 warps, before chains split) ----
    for (int j = tid; j < NH; j += TPB) { sm.svf[0][j] = x_f[j]; sm.svf[1][j] = x_b[j]; }
    __syncthreads();
    #pragma unroll
    for (int r2 = 0; r2 < 2; r2++) {
        const int row = blockIdx.x * ROWS_PB + warp * 2 + r2;
        float a0, a1;
        wdot_f2<NH/4>(reinterpret_cast<const float4*>(i2h_W + (size_t)row * K2),
                      reinterpret_cast<const float4*>(sm.svf[0]),
                      reinterpret_cast<const float4*>(sm.svf[1]), lane, a0, a1);
        if (lane == 0) { g_xd[0][row] = a0; g_xd[1][row] = a1; }
    }
    __syncthreads();                       // svf -> ode union reuse safety

    // ---- publish v0 per chain ----
    if (is_red) {
        __stcg(reinterpret_cast<unsigned short*>(&g_v[ch][red_rw]),
               __half_as_ushort(__float2half(hbase)));
        __syncwarp();
        if (lane == 0) chain_release(ctr);
    }
    a_prefetch(abuf, A1);

    // ---- RK4 ODE: two independent 120-phase chains ----
    unsigned ctgt = GRIDB;
    const int nphase = nsteps * 4;
    for (int p = 0; p < nphase; p++) {
        const int stage = p & 3;

        // ======== layer 1: u = tanh(W1 @ v + b1) ========
        chain_wait(ctr, ctgt, lane); ctgt += GRIDB;
        asm volatile("bar.sync %0, 256;" :: "r"(2 + ch) : "memory");
        {   // 8 KB chain B-stage
            const uint4* src = reinterpret_cast<const uint4*>(&g_v[ch][0]);
            uint4* dst = reinterpret_cast<uint4*>(sm.ode.sB[ch]);
            dst[ctid]       = __ldcg(src + ctid);
            dst[ctid + 256] = __ldcg(src + ctid + 256);
        }
        asm volatile("bar.sync %0, 256;" :: "r"(2 + ch) : "memory");
        ode_mma64(abuf, A1, sm.ode.sB[ch], sm.ode.part[ch], rg, kc, lane);
        asm volatile("bar.sync %0, 256;" :: "r"(2 + ch) : "memory");
        a_prefetch(abuf, A2);
        if (is_red) {
            float acc = sm.ode.part[ch][lane]      + sm.ode.part[ch][32 + lane]
                      + sm.ode.part[ch][64 + lane] + sm.ode.part[ch][96 + lane];
            const float u = tanh_fast(acc + bias1);
            __stcg(reinterpret_cast<unsigned short*>(&g_u[ch][red_rw]),
                   __half_as_ushort(__float2half(u)));
            __syncwarp();
            if (lane == 0) chain_release(ctr);
        }

        // ======== layer 2: k = W2 @ u + b2; RK4 state update ========
        chain_wait(ctr, ctgt, lane); ctgt += GRIDB;
        asm volatile("bar.sync %0, 256;" :: "r"(2 + ch) : "memory");
        {
            const uint4* src = reinterpret_cast<const uint4*>(&g_u[ch][0]);
            uint4* dst = reinterpret_cast<uint4*>(sm.ode.sB[ch]);
            dst[ctid]       = __ldcg(src + ctid);
            dst[ctid + 256] = __ldcg(src + ctid + 256);
        }
        asm volatile("bar.sync %0, 256;" :: "r"(2 + ch) : "memory");
        ode_mma64(abuf, A2, sm.ode.sB[ch], sm.ode.part[ch], rg, kc, lane);
        asm volatile("bar.sync %0, 256;" :: "r"(2 + ch) : "memory");
        a_prefetch(abuf, A1);
        if (is_red) {
            float acc = sm.ode.part[ch][lane]      + sm.ode.part[ch][32 + lane]
                      + sm.ode.part[ch][64 + lane] + sm.ode.part[ch][96 + lane];
            const float kv = acc + bias2;
            const float dt = sdt[ch][p >> 2];
            float vnext;
            if (stage == 0)      { ksumr = kv;           vnext = hbase + 0.5f*dt*kv; }
            else if (stage == 1) { ksumr += 2.f*kv;      vnext = hbase + 0.5f*dt*kv; }
            else if (stage == 2) { ksumr += 2.f*kv;      vnext = hbase + dt*kv; }
            else {
                ksumr += kv;
                hbase += (dt * (1.0f/6.0f)) * ksumr;
                vnext = hbase;
                if (p == nphase - 1)
                    __stcg(&g_vfin[ch][red_rw], hbase);
            }
            __stcg(reinterpret_cast<unsigned short*>(&g_v[ch][red_rw]),
                   __half_as_ushort(__float2half(vnext)));
            __syncwarp();
            if (lane == 0) chain_release(ctr);
        }
    }

    // ---- GRU phase 0: g = sigmoid(xd + W_h @ h_fin + b) ----
    bar_arrive();
    bar_wait(target);
    {
        const float4* src = reinterpret_cast<const float4*>(&g_vfin[0][0]);
        float4* dst = reinterpret_cast<float4*>(&sm.svf[0][0]);
        #pragma unroll
        for (int r = 0; r < 4; r++) dst[tid + r * TPB] = __ldcg(src + tid + r * TPB);
    }
    __syncthreads();
    #pragma unroll
    for (int r2 = 0; r2 < 2; r2++) {
        const int row = blockIdx.x * ROWS_PB + warp * 2 + r2;
        float a0, a1;
        wdot_f2<NH/4>(reinterpret_cast<const float4*>(i2h_W + (size_t)row * K2 + NH),
                      reinterpret_cast<const float4*>(sm.svf[0]),
                      reinterpret_cast<const float4*>(sm.svf[1]), lane, a0, a1);
        if (lane == 0) {
            const float bb = i2h_b[row];
            __stcg(&g_g[0][row], 1.f / (1.f + expf(-(g_xd[0][row] + a0 + bb))));
            __stcg(&g_g[1][row], 1.f / (1.f + expf(-(g_xd[1][row] + a1 + bb))));
        }
    }
    bar_arrive();

    // ---- GRU phase 1: h_hat = tanh(xd + W_h @ (g .* h_fin) + b) ----
    bar_wait(target);
    #pragma unroll
    for (int b = 0; b < 2; b++)
        for (int j = tid; j < NH; j += TPB)
            sm.svf[b][j] = __ldcg(&g_g[b][j]) * __ldcg(&g_vfin[b][j]);
    __syncthreads();
    #pragma unroll
    for (int r2 = 0; r2 < 2; r2++) {
        const int row = blockIdx.x * ROWS_PB + warp * 2 + r2;
        float a0, a1;
        wdot_f2<NH/4>(reinterpret_cast<const float4*>(i2h_W + (size_t)row * K2 + NH),
                      reinterpret_cast<const float4*>(sm.svf[0]),
                      reinterpret_cast<const float4*>(sm.svf[1]), lane, a0, a1);
        if (lane == 0) {
            const float bb = i2h_b[row];
            __stcg(&g_hhat[0][row], tanhf(g_xd[0][row] + a0 + bb));
            __stcg(&g_hhat[1][row], tanhf(g_xd[1][row] + a1 + bb));
        }
    }
    bar_arrive();

    // ---- GRU blend + emit h_f / h_b ----
    bar_wait(target);
    {
        int i = blockIdx.x * TPB + tid;
        if (i < 2 * NH) {
            const int b = i >> 12, j = i & (NH - 1);
            const float g  = __ldcg(&g_g[b][j]);
            const float hn = g * __ldcg(&g_vfin[b][j]) + (1.f - g) * __ldcg(&g_hhat[b][j]);
            __stcg(&g_hnew[b][j], hn);
            out[NH + i] = hn;
        }
    }
    bar_arrive();

    // ---- output matvec ----
    bar_wait(target);
    {
        const float4* src = reinterpret_cast<const float4*>(&g_hnew[0][0]);
        float4* dst = reinterpret_cast<float4*>(&sm.svf[0][0]);
        #pragma unroll
        for (int r = 0; r < 4; r++) dst[tid + r * TPB] = __ldcg(src + tid + r * TPB);
    }
    __syncthreads();
    #pragma unroll
    for (int r2 = 0; r2 < 2; r2++) {
        const int row = blockIdx.x * ROWS_PB + warp * 2 + r2;
        float a = wdot_f1<K2/4>(reinterpret_cast<const float4*>(h2o_W + (size_t)row * K2),
                                reinterpret_cast<const float4*>(&sm.svf[0][0]), lane);
        if (lane == 0) out[row] = a + h2o_b[row];
    }
}

extern "C" void kernel_launch(void* const* d_in, const int* in_sizes, int n_in,
                              void* d_out, int out_size)
{
    const float* x_f   = (const float*)d_in[0];
    const float* x_b   = (const float*)d_in[1];
    const float* h_f   = (const float*)d_in[2];
    const float* h_b   = (const float*)d_in[3];
    const float* t_f   = (const float*)d_in[4];
    const float* t_b   = (const float*)d_in[5];
    const float* i2h_W = (const float*)d_in[6];
    const float* i2h_b = (const float*)d_in[7];
    const float* h2o_W = (const float*)d_in[8];
    const float* h2o_b = (const float*)d_in[9];
    const float* f_W1  = (const float*)d_in[10];
    const float* f_b1  = (const float*)d_in[11];
    const float* f_W2  = (const float*)d_in[12];
    const float* f_b2  = (const float*)d_in[13];
    float* out = (float*)d_out;

    const int T = in_sizes[4];
    const int nsteps = T - 1;

    __half *w1p, *w2p;
    cudaGetSymbolAddress((void**)&w1p, g_W1p);
    cudaGetSymbolAddress((void**)&w2p, g_W2p);

    const int permBlocks = (NH / 16) * (NH / 16) * 32 / 256;   // 8192
    k_perm<<<permBlocks, 256>>>(f_W1, w1p);
    k_perm<<<permBlocks, 256>>>(f_W2, w2p);
    k_reset<<<1, 64>>>();

    k_all<<<GRIDB, TPB>>>(f_b1, f_b2, i2h_W, i2h_b, h2o_W, h2o_b,
                          x_f, x_b, h_f, h_b, t_f, t_b, out, nsteps);
}

// round 14
// speedup vs baseline: 1.5431x; 1.5431x over previous
#include <cuda_runtime.h>
#include <cuda_fp16.h>
#include <math.h>
#include <stdint.h>

#define NH     4096
#define K2     8192
#define GRIDB  128          // blocks (<= 148 SMs -> co-resident, barrier safe)
#define TPB    512          // 16 warps
#define ROWS_PB 32

// dynamic smem: 64 KB cp.async A-buffer (aliased by 32 KB svf in GRU phases)
#define ABUF_BYTES (16 * 8 * 512)     // 16 warps x 8 frags x 512 B = 65536

// ---------------- persistent device scratch (no allocations) ----------------
__device__ __half g_W1p[(size_t)NH * NH];   // fp16 f_W1, fragment-major
__device__ __half g_W2p[(size_t)NH * NH];   // fp16 f_W2, fragment-major
__device__ __half g_vh[2 * NH];             // current ODE input vector v (fp16)
__device__ __half g_uh[2 * NH];             // tanh hidden u (fp16)
__device__ float  g_vfin[2][NH];            // h after full integration (fp32)
__device__ float  g_g[2][NH];
__device__ float  g_hhat[2][NH];
__device__ float  g_hnew[2][NH];
__device__ float  g_xd[2][NH];
__device__ unsigned g_arrive;

__global__ void k_reset() { g_arrive = 0u; }

// ------- fp32 -> fp16 + permute to mma A-fragment-major layout --------------
__global__ __launch_bounds__(256)
void k_perm(const float* __restrict__ W, __half* __restrict__ P)
{
    const int gidx = blockIdx.x * 256 + threadIdx.x;   // tile*32 + lane
    const int lane = gidx & 31, tile = gidx >> 5;
    const int rg = tile >> 8, kt = tile & 255;
    const int R0 = rg * 16, C0 = kt * 16;
    const int g = lane >> 2, q = lane & 3;
    const float2* r0p = reinterpret_cast<const float2*>(W + (size_t)(R0 + g)     * NH + C0 + 2*q);
    const float2* r8p = reinterpret_cast<const float2*>(W + (size_t)(R0 + 8 + g) * NH + C0 + 2*q);
    float2 a01 = r0p[0];
    float2 a23 = r8p[0];
    float2 a45 = r0p[4];
    float2 a67 = r8p[4];
    __half2 h0 = __floats2half2_rn(a01.x, a01.y);
    __half2 h1 = __floats2half2_rn(a23.x, a23.y);
    __half2 h2 = __floats2half2_rn(a45.x, a45.y);
    __half2 h3 = __floats2half2_rn(a67.x, a67.y);
    uint4 o;
    o.x = *reinterpret_cast<uint32_t*>(&h0);
    o.y = *reinterpret_cast<uint32_t*>(&h1);
    o.z = *reinterpret_cast<uint32_t*>(&h2);
    o.w = *reinterpret_cast<uint32_t*>(&h3);
    reinterpret_cast<uint4*>(P)[gidx] = o;
}

// ---------------- full-grid barrier: release-red / acquire-poll -------------
__device__ __forceinline__ void bar_arrive()
{
    __syncthreads();
    if (threadIdx.x == 0) {
        unsigned* p = &g_arrive;
        asm volatile("red.release.gpu.global.add.u32 [%0], 1;" :: "l"(p) : "memory");
    }
}
__device__ __forceinline__ void bar_wait(unsigned& target)
{
    if (threadIdx.x == 0) {
        unsigned* p = &g_arrive;
        unsigned v;
        do {
            asm volatile("ld.acquire.gpu.global.u32 %0, [%1];" : "=r"(v) : "l"(p) : "memory");
        } while (v < target);
    }
    __syncthreads();
    target += GRIDB;
}

// ---------------- cp.async helpers ----------------
__device__ __forceinline__ void cp16(uint32_t smem_dst, const void* gsrc)
{
    asm volatile("cp.async.cg.shared.global [%0], [%1], 16;"
                 :: "r"(smem_dst), "l"(gsrc) : "memory");
}
__device__ __forceinline__ void cp_commit()
{
    asm volatile("cp.async.commit_group;" ::: "memory");
}
__device__ __forceinline__ void cp_wait0()
{
    asm volatile("cp.async.wait_group 0;" ::: "memory");
}

// Issue frags 8..15 of matvec A into this warp's smem buffer region.
__device__ __forceinline__ void a_prefetch_smem(uint32_t sbase, const uint4* A, int lane)
{
    #pragma unroll
    for (int s = 0; s < 8; s++)
        cp16(sbase + s * 512 + lane * 16, (const void*)(A + (size_t)(8 + s) * 32));
    cp_commit();
}

// ---------------- HMMA m16n8k16 fp32-accum ----------------
__device__ __forceinline__ void mma16816(float c[4], const uint4& a,
                                         uint32_t b0, uint32_t b1)
{
    asm volatile(
        "mma.sync.aligned.m16n8k16.row.col.f32.f16.f16.f32 "
        "{%0,%1,%2,%3}, {%4,%5,%6,%7}, {%8,%9}, {%0,%1,%2,%3};"
        : "+f"(c[0]), "+f"(c[1]), "+f"(c[2]), "+f"(c[3])
        : "r"(a.x), "r"(a.y), "r"(a.z), "r"(a.w), "r"(b0), "r"(b1));
}

__device__ __forceinline__ const uint4* a_ptr(const __half* Wp, int warp, int lane)
{
    const int rg = warp >> 3, kc = warp & 7;
    const int rg_glob = blockIdx.x * 2 + rg;
    return reinterpret_cast<const uint4*>(Wp)
         + ((size_t)rg_glob * 256 + kc * 32) * 32 + lane;
}

__device__ __forceinline__ void a_prefetch(uint4* abuf, const uint4* A)
{
    #pragma unroll
    for (int p = 0; p < 8; p++) abuf[p] = A[p * 32];
}

// mma mainloop: steps 0-7 reg ring (pre-barrier prefetch), steps 8-15 from
// cp.async smem buffer (filled last phase), steps 16-31 in-loop ring refill.
__device__ __forceinline__ void ode_mma(uint4* abuf, const uint4* A,
                                        const uint4* __restrict__ sbuf,  // warp region + lane
                                        const __half* __restrict__ svh,
                                        float* __restrict__ part,
                                        int warp, int lane)
{
    const int rg = warp >> 3, kc = warp & 7;
    const int n = lane >> 2, q = lane & 3;
    const bool hasB = (n < 2);
    const __half* vb = svh + (hasB ? n : 0) * NH + kc * 512 + q * 2;

    float c0[4] = {0.f,0.f,0.f,0.f}, c1[4] = {0.f,0.f,0.f,0.f};
    #pragma unroll
    for (int s = 0; s < 32; s++) {
        uint4 a;
        if (s < 8)       a = abuf[s];
        else if (s < 16) a = sbuf[(s - 8) * 32];
        else             a = abuf[s & 7];
        // refill ring: at steps 8..23, load for step s+8 into slot (s+8)&7
        if (s >= 8 && s < 24) abuf[(s + 8) & 7] = A[(size_t)(s + 8) * 32];
        uint32_t b0 = 0u, b1 = 0u;
        if (hasB) {
            b0 = *reinterpret_cast<const uint32_t*>(vb + s * 16);
            b1 = *reinterpret_cast<const uint32_t*>(vb + s * 16 + 8);
        }
        if (s & 1) mma16816(c1, a, b0, b1);
        else       mma16816(c0, a, b0, b1);
    }
    if (q == 0) {
        const int r = rg * 16 + n;
        part[(kc * 32 + r)     * 2 + 0] = c0[0] + c1[0];
        part[(kc * 32 + r)     * 2 + 1] = c0[1] + c1[1];
        part[(kc * 32 + r + 8) * 2 + 0] = c0[2] + c1[2];
        part[(kc * 32 + r + 8) * 2 + 1] = c0[3] + c1[3];
    }
}

// ---------------- fp32 warp dots (GRU / out) ----------------
template<int K4>
__device__ __forceinline__ void wdot_f2(const float4* __restrict__ Wr,
                                        const float4* __restrict__ v0,
                                        const float4* __restrict__ v1,
                                        int lane, float& a0, float& a1)
{
    a0 = 0.f; a1 = 0.f;
    #pragma unroll 8
    for (int i = lane; i < K4; i += 32) {
        float4 w = Wr[i], x0 = v0[i], x1 = v1[i];
        a0 += w.x*x0.x + w.y*x0.y + w.z*x0.z + w.w*x0.w;
        a1 += w.x*x1.x + w.y*x1.y + w.z*x1.z + w.w*x1.w;
    }
    #pragma unroll
    for (int off = 16; off; off >>= 1) {
        a0 += __shfl_down_sync(0xffffffffu, a0, off);
        a1 += __shfl_down_sync(0xffffffffu, a1, off);
    }
}

template<int K4>
__device__ __forceinline__ float wdot_f1(const float4* __restrict__ Wr,
                                         const float4* __restrict__ v, int lane)
{
    float a = 0.f;
    #pragma unroll 8
    for (int i = lane; i < K4; i += 32) {
        float4 w = Wr[i], x = v[i];
        a += w.x*x.x + w.y*x.y + w.z*x.z + w.w*x.w;
    }
    #pragma unroll
    for (int off = 16; off; off >>= 1) a += __shfl_down_sync(0xffffffffu, a, off);
    return a;
}

// ---------------- the whole model in one persistent kernel ------------------
__global__ __launch_bounds__(TPB, 1)
void k_all(const float* __restrict__ f_b1, const float* __restrict__ f_b2,
           const float* __restrict__ i2h_W, const float* __restrict__ i2h_b,
           const float* __restrict__ h2o_W, const float* __restrict__ h2o_b,
           const float* __restrict__ x_f, const float* __restrict__ x_b,
           const float* __restrict__ h_f, const float* __restrict__ h_b,
           const float* __restrict__ tf, const float* __restrict__ tb,
           float* __restrict__ out, int nsteps)
{
    extern __shared__ unsigned char smem_dyn[];   // 64 KB A-buffer / 32 KB svf
    __shared__ __half svh[2 * NH];                // 16 KB (ODE v / u staging)
    __shared__ float  part[8 * 32 * 2];           //  2 KB (ODE partials)

    const int tid  = threadIdx.x;
    const int warp = tid >> 5, lane = tid & 31;
    unsigned target = GRIDB;
    uint4 abuf[8];

    const uint4* A1 = a_ptr(g_W1p, warp, lane);
    const uint4* A2 = a_ptr(g_W2p, warp, lane);
    const uint32_t sbase =
        (uint32_t)__cvta_generic_to_shared(smem_dyn) + warp * 8 * 512;
    const uint4* sbuf =
        reinterpret_cast<const uint4*>(smem_dyn) + warp * 256 + lane;
    float* svf = reinterpret_cast<float*>(smem_dyn);   // GRU alias (32 KB)

    // ---- reducer persistent state (threads 0..63: row rw, batch b) ----
    const int red_r  = tid >> 1;
    const int red_b  = tid & 1;
    const int red_rw = blockIdx.x * ROWS_PB + red_r;
    float hbase = 0.f, ksumr = 0.f, bias1 = 0.f, bias2 = 0.f;
    if (tid < 64) {
        hbase = (red_b ? h_b : h_f)[red_rw];
        bias1 = f_b1[red_rw];
        bias2 = f_b2[red_rw];
        __stcg(reinterpret_cast<unsigned short*>(&g_vh[red_b * NH + red_rw]),
               __half_as_ushort(__float2half(hbase)));
    }

    // ---- GRU x-half dot (independent of ODE) ----
    for (int j = tid; j < NH; j += TPB) { svf[j] = x_f[j]; svf[NH + j] = x_b[j]; }
    __syncthreads();
    #pragma unroll
    for (int r2 = 0; r2 < 2; r2++) {
        const int row = blockIdx.x * ROWS_PB + warp * 2 + r2;
        float a0, a1;
        wdot_f2<NH/4>(reinterpret_cast<const float4*>(i2h_W + (size_t)row * K2),
                      reinterpret_cast<const float4*>(svf),
                      reinterpret_cast<const float4*>(svf + NH), lane, a0, a1);
        if (lane == 0) { g_xd[0][row] = a0; g_xd[1][row] = a1; }
    }
    __syncthreads();                       // svf -> A-buffer reuse safety
    a_prefetch(abuf, A1);                  // frags 0-7 via registers
    a_prefetch_smem(sbase, A1, lane);      // frags 8-15 via cp.async
    bar_arrive();

    // ---- RK4 ODE: 120 phases ----
    for (int s = 0; s < nsteps; s++) {
        for (int stage = 0; stage < 4; stage++) {
            // ======== layer 1: u = tanh(W1 @ v + b1) ========
            bar_wait(target);
            {   // 16 KB .cg copy: g_vh -> smem
                const uint4* src = reinterpret_cast<const uint4*>(&g_vh[0]);
                uint4* dst = reinterpret_cast<uint4*>(svh);
                dst[tid]       = __ldcg(src + tid);
                dst[tid + TPB] = __ldcg(src + tid + TPB);
            }
            cp_wait0();                    // frags 8-15 landed (issued last phase)
            __syncthreads();
            ode_mma(abuf, A1, sbuf, svh, part, warp, lane);
            __syncthreads();
            a_prefetch(abuf, A2);          // next matvec: frags 0-7 (regs)
            a_prefetch_smem(sbase, A2, lane);  // frags 8-15 (cp.async)
            if (tid < 64) {
                float acc = 0.f;
                #pragma unroll
                for (int kc = 0; kc < 8; kc++) acc += part[(kc * 32 + red_r) * 2 + red_b];
                const float u = tanhf(acc + bias1);
                __stcg(reinterpret_cast<unsigned short*>(&g_uh[red_b * NH + red_rw]),
                       __half_as_ushort(__float2half(u)));
            }
            bar_arrive();

            // ======== layer 2: k = W2 @ u + b2; RK4 state update ========
            bar_wait(target);
            {   // 16 KB .cg copy: g_uh -> smem
                const uint4* src = reinterpret_cast<const uint4*>(&g_uh[0]);
                uint4* dst = reinterpret_cast<uint4*>(svh);
                dst[tid]       = __ldcg(src + tid);
                dst[tid + TPB] = __ldcg(src + tid + TPB);
            }
            cp_wait0();
            __syncthreads();
            ode_mma(abuf, A2, sbuf, svh, part, warp, lane);
            __syncthreads();
            a_prefetch(abuf, A1);
            a_prefetch_smem(sbase, A1, lane);
            if (tid < 64) {
                float acc = 0.f;
                #pragma unroll
                for (int kc = 0; kc < 8; kc++) acc += part[(kc * 32 + red_r) * 2 + red_b];
                const float kv = acc + bias2;
                const float* t = red_b ? tb : tf;
                const float dt = t[s+1] - t[s];
                float vnext;
                if (stage == 0)      { ksumr = kv;           vnext = hbase + 0.5f*dt*kv; }
                else if (stage == 1) { ksumr += 2.f*kv;      vnext = hbase + 0.5f*dt*kv; }
                else if (stage == 2) { ksumr += 2.f*kv;      vnext = hbase + dt*kv; }
                else {
                    ksumr += kv;
                    hbase += (dt * (1.0f/6.0f)) * ksumr;
                    vnext = hbase;
                    if (s == nsteps - 1)
                        __stcg(&g_vfin[red_b][red_rw], hbase);
                }
                __stcg(reinterpret_cast<unsigned short*>(&g_vh[red_b * NH + red_rw]),
                       __half_as_ushort(__float2half(vnext)));
            }
            bar_arrive();
        }
    }

    cp_wait0();                            // drain last cp.async before svf reuse

    // ---- GRU phase 0: g = sigmoid(xd + W_h @ h_fin + b) ----
    bar_wait(target);
    {
        const float4* src = reinterpret_cast<const float4*>(&g_vfin[0][0]);
        float4* dst = reinterpret_cast<float4*>(svf);
        #pragma unroll
        for (int r = 0; r < 4; r++) dst[tid + r * TPB] = __ldcg(src + tid + r * TPB);
    }
    __syncthreads();
    #pragma unroll
    for (int r2 = 0; r2 < 2; r2++) {
        const int row = blockIdx.x * ROWS_PB + warp * 2 + r2;
        float a0, a1;
        wdot_f2<NH/4>(reinterpret_cast<const float4*>(i2h_W + (size_t)row * K2 + NH),
                      reinterpret_cast<const float4*>(svf),
                      reinterpret_cast<const float4*>(svf + NH), lane, a0, a1);
        if (lane == 0) {
            const float bb = i2h_b[row];
            __stcg(&g_g[0][row], 1.f / (1.f + expf(-(g_xd[0][row] + a0 + bb))));
            __stcg(&g_g[1][row], 1.f / (1.f + expf(-(g_xd[1][row] + a1 + bb))));
        }
    }
    bar_arrive();

    // ---- GRU phase 1: h_hat = tanh(xd + W_h @ (g .* h_fin) + b) ----
    bar_wait(target);
    for (int j = tid; j < NH; j += TPB) {
        svf[j]      = __ldcg(&g_g[0][j]) * __ldcg(&g_vfin[0][j]);
        svf[NH + j] = __ldcg(&g_g[1][j]) * __ldcg(&g_vfin[1][j]);
    }
    __syncthreads();
    #pragma unroll
    for (int r2 = 0; r2 < 2; r2++) {
        const int row = blockIdx.x * ROWS_PB + warp * 2 + r2;
        float a0, a1;
        wdot_f2<NH/4>(reinterpret_cast<const float4*>(i2h_W + (size_t)row * K2 + NH),
                      reinterpret_cast<const float4*>(svf),
                      reinterpret_cast<const float4*>(svf + NH), lane, a0, a1);
        if (lane == 0) {
            const float bb = i2h_b[row];
            __stcg(&g_hhat[0][row], tanhf(g_xd[0][row] + a0 + bb));
            __stcg(&g_hhat[1][row], tanhf(g_xd[1][row] + a1 + bb));
        }
    }
    bar_arrive();

    // ---- GRU blend + emit h_f / h_b ----
    bar_wait(target);
    {
        int i = blockIdx.x * TPB + tid;
        if (i < 2 * NH) {
            const int b = i >> 12, j = i & (NH - 1);
            const float g  = __ldcg(&g_g[b][j]);
            const float hn = g * __ldcg(&g_vfin[b][j]) + (1.f - g) * __ldcg(&g_hhat[b][j]);
            __stcg(&g_hnew[b][j], hn);
            out[NH + i] = hn;
        }
    }
    bar_arrive();

    // ---- output matvec ----
    bar_wait(target);
    {
        const float4* src = reinterpret_cast<const float4*>(&g_hnew[0][0]);
        float4* dst = reinterpret_cast<float4*>(svf);
        #pragma unroll
        for (int r = 0; r < 4; r++) dst[tid + r * TPB] = __ldcg(src + tid + r * TPB);
    }
    __syncthreads();
    #pragma unroll
    for (int r2 = 0; r2 < 2; r2++) {
        const int row = blockIdx.x * ROWS_PB + warp * 2 + r2;
        float a = wdot_f1<K2/4>(reinterpret_cast<const float4*>(h2o_W + (size_t)row * K2),
                                reinterpret_cast<const float4*>(svf), lane);
        if (lane == 0) out[row] = a + h2o_b[row];
    }
}

extern "C" void kernel_launch(void* const* d_in, const int* in_sizes, int n_in,
                              void* d_out, int out_size)
{
    const float* x_f   = (const float*)d_in[0];
    const float* x_b   = (const float*)d_in[1];
    const float* h_f   = (const float*)d_in[2];
    const float* h_b   = (const float*)d_in[3];
    const float* t_f   = (const float*)d_in[4];
    const float* t_b   = (const float*)d_in[5];
    const float* i2h_W = (const float*)d_in[6];
    const float* i2h_b = (const float*)d_in[7];
    const float* h2o_W = (const float*)d_in[8];
    const float* h2o_b = (const float*)d_in[9];
    const float* f_W1  = (const float*)d_in[10];
    const float* f_b1  = (const float*)d_in[11];
    const float* f_W2  = (const float*)d_in[12];
    const float* f_b2  = (const float*)d_in[13];
    float* out = (float*)d_out;

    const int T = in_sizes[4];
    const int nsteps = T - 1;

    __half *w1p, *w2p;
    cudaGetSymbolAddress((void**)&w1p, g_W1p);
    cudaGetSymbolAddress((void**)&w2p, g_W2p);

    cudaFuncSetAttribute((const void*)k_all,
                         cudaFuncAttributeMaxDynamicSharedMemorySize, ABUF_BYTES);

    const int permBlocks = (NH / 16) * (NH / 16) * 32 / 256;   // 8192
    k_perm<<<permBlocks, 256>>>(f_W1, w1p);
    k_perm<<<permBlocks, 256>>>(f_W2, w2p);
    k_reset<<<1, 1>>>();

    k_all<<<GRIDB, TPB, ABUF_BYTES>>>(f_b1, f_b2, i2h_W, i2h_b, h2o_W, h2o_b,
                                      x_f, x_b, h_f, h_b, t_f, t_b, out, nsteps);
}

// round 15
// speedup vs baseline: 1.5861x; 1.0279x over previous
#include <cuda_runtime.h>
#include <cuda_fp16.h>
#include <math.h>
#include <stdint.h>

#define NH     4096
#define K2     8192
#define GRIDB  256          // 2 blocks per SM region (<= 2*148 -> co-resident)
#define TPB    256          // 8 warps
#define ROWS_PB 16

// ---------------- persistent device scratch (no allocations) ----------------
__device__ __half g_W1p[(size_t)NH * NH];   // fp16 f_W1, fragment-major
__device__ __half g_W2p[(size_t)NH * NH];   // fp16 f_W2, fragment-major
__device__ __half g_vh[2 * NH];             // current ODE input vector v (fp16)
__device__ __half g_uh[2 * NH];             // tanh hidden u (fp16)
__device__ float  g_vfin[2][NH];            // h after full integration (fp32)
__device__ float  g_g[2][NH];
__device__ float  g_hhat[2][NH];
__device__ float  g_hnew[2][NH];
__device__ float  g_xd[2][NH];
__device__ unsigned g_arrive;

__global__ void k_reset() { g_arrive = 0u; }

// ------- fp32 -> fp16 + permute to mma A-fragment-major layout --------------
__global__ __launch_bounds__(256)
void k_perm(const float* __restrict__ W, __half* __restrict__ P)
{
    const int gidx = blockIdx.x * 256 + threadIdx.x;   // tile*32 + lane
    const int lane = gidx & 31, tile = gidx >> 5;
    const int rg = tile >> 8, kt = tile & 255;
    const int R0 = rg * 16, C0 = kt * 16;
    const int g = lane >> 2, q = lane & 3;
    const float2* r0p = reinterpret_cast<const float2*>(W + (size_t)(R0 + g)     * NH + C0 + 2*q);
    const float2* r8p = reinterpret_cast<const float2*>(W + (size_t)(R0 + 8 + g) * NH + C0 + 2*q);
    float2 a01 = r0p[0];
    float2 a23 = r8p[0];
    float2 a45 = r0p[4];
    float2 a67 = r8p[4];
    __half2 h0 = __floats2half2_rn(a01.x, a01.y);
    __half2 h1 = __floats2half2_rn(a23.x, a23.y);
    __half2 h2 = __floats2half2_rn(a45.x, a45.y);
    __half2 h3 = __floats2half2_rn(a67.x, a67.y);
    uint4 o;
    o.x = *reinterpret_cast<uint32_t*>(&h0);
    o.y = *reinterpret_cast<uint32_t*>(&h1);
    o.z = *reinterpret_cast<uint32_t*>(&h2);
    o.w = *reinterpret_cast<uint32_t*>(&h3);
    reinterpret_cast<uint4*>(P)[gidx] = o;
}

// ---------------- full-grid barrier: release-red / acquire-poll -------------
__device__ __forceinline__ void bar_arrive()
{
    __syncthreads();
    if (threadIdx.x == 0) {
        unsigned* p = &g_arrive;
        asm volatile("red.release.gpu.global.add.u32 [%0], 1;" :: "l"(p) : "memory");
    }
}
__device__ __forceinline__ void bar_wait(unsigned& target)
{
    if (threadIdx.x == 0) {
        unsigned* p = &g_arrive;
        unsigned v;
        do {
            asm volatile("ld.acquire.gpu.global.u32 %0, [%1];" : "=r"(v) : "l"(p) : "memory");
        } while (v < target);
    }
    __syncthreads();
    target += GRIDB;
}

// ---------------- HMMA m16n8k16 fp32-accum ----------------
__device__ __forceinline__ void mma16816(float c[4], const uint4& a,
                                         uint32_t b0, uint32_t b1)
{
    asm volatile(
        "mma.sync.aligned.m16n8k16.row.col.f32.f16.f16.f32 "
        "{%0,%1,%2,%3}, {%4,%5,%6,%7}, {%8,%9}, {%0,%1,%2,%3};"
        : "+f"(c[0]), "+f"(c[1]), "+f"(c[2]), "+f"(c[3])
        : "r"(a.x), "r"(a.y), "r"(a.z), "r"(a.w), "r"(b0), "r"(b1));
}

// 8 warps = 8 kc slices (K=512 each) of this block's single 16-row group.
__device__ __forceinline__ const uint4* a_ptr(const __half* Wp, int warp, int lane)
{
    return reinterpret_cast<const uint4*>(Wp)
         + ((size_t)blockIdx.x * 256 + warp * 32) * 32 + lane;
}

__device__ __forceinline__ void a_prefetch(uint4* abuf, const uint4* A)
{
    #pragma unroll
    for (int p = 0; p < 8; p++) abuf[p] = A[p * 32];
}

// mma mainloop: ring 8, 2 accumulator chains, 32 steps (K=512 per warp)
__device__ __forceinline__ void ode_mma(uint4* abuf, const uint4* A,
                                        const __half* __restrict__ svh,   // [2][NH] flat
                                        float* __restrict__ part,
                                        int warp, int lane)
{
    const int n = lane >> 2, q = lane & 3;
    const bool hasB = (n < 2);
    const __half* vb = svh + (hasB ? n : 0) * NH + warp * 512 + q * 2;

    float c0[4] = {0.f,0.f,0.f,0.f}, c1[4] = {0.f,0.f,0.f,0.f};
    #pragma unroll
    for (int s = 0; s < 32; s++) {
        uint4 a = abuf[s & 7];
        if (s < 24) abuf[s & 7] = A[(size_t)(s + 8) * 32];
        uint32_t b0 = 0u, b1 = 0u;
        if (hasB) {
            b0 = *reinterpret_cast<const uint32_t*>(vb + s * 16);
            b1 = *reinterpret_cast<const uint32_t*>(vb + s * 16 + 8);
        }
        if (s & 1) mma16816(c1, a, b0, b1);
        else       mma16816(c0, a, b0, b1);
    }
    if (q == 0) {
        part[(warp * 16 + n)     * 2 + 0] = c0[0] + c1[0];
        part[(warp * 16 + n)     * 2 + 1] = c0[1] + c1[1];
        part[(warp * 16 + n + 8) * 2 + 0] = c0[2] + c1[2];
        part[(warp * 16 + n + 8) * 2 + 1] = c0[3] + c1[3];
    }
}

// ---------------- fp32 warp dots (GRU / out) ----------------
template<int K4>
__device__ __forceinline__ void wdot_f2(const float4* __restrict__ Wr,
                                        const float4* __restrict__ v0,
                                        const float4* __restrict__ v1,
                                        int lane, float& a0, float& a1)
{
    a0 = 0.f; a1 = 0.f;
    #pragma unroll 8
    for (int i = lane; i < K4; i += 32) {
        float4 w = Wr[i], x0 = v0[i], x1 = v1[i];
        a0 += w.x*x0.x + w.y*x0.y + w.z*x0.z + w.w*x0.w;
        a1 += w.x*x1.x + w.y*x1.y + w.z*x1.z + w.w*x1.w;
    }
    #pragma unroll
    for (int off = 16; off; off >>= 1) {
        a0 += __shfl_down_sync(0xffffffffu, a0, off);
        a1 += __shfl_down_sync(0xffffffffu, a1, off);
    }
}

template<int K4>
__device__ __forceinline__ float wdot_f1(const float4* __restrict__ Wr,
                                         const float4* __restrict__ v, int lane)
{
    float a = 0.f;
    #pragma unroll 8
    for (int i = lane; i < K4; i += 32) {
        float4 w = Wr[i], x = v[i];
        a += w.x*x.x + w.y*x.y + w.z*x.z + w.w*x.w;
    }
    #pragma unroll
    for (int off = 16; off; off >>= 1) a += __shfl_down_sync(0xffffffffu, a, off);
    return a;
}

// ---------------- the whole model in one persistent kernel ------------------
__global__ __launch_bounds__(TPB, 2)
void k_all(const float* __restrict__ f_b1, const float* __restrict__ f_b2,
           const float* __restrict__ i2h_W, const float* __restrict__ i2h_b,
           const float* __restrict__ h2o_W, const float* __restrict__ h2o_b,
           const float* __restrict__ x_f, const float* __restrict__ x_b,
           const float* __restrict__ h_f, const float* __restrict__ h_b,
           const float* __restrict__ tf, const float* __restrict__ tb,
           float* __restrict__ out, int nsteps)
{
    __shared__ __half svh[2 * NH];         // 16 KB (ODE v / u staging)
    __shared__ union {
        float svf[2][NH];                  // 32 KB (GRU / out)
        float part[8 * 16 * 2];            //  1 KB (ODE partials)
    } sm;

    const int tid  = threadIdx.x;
    const int warp = tid >> 5, lane = tid & 31;
    unsigned target = GRIDB;
    uint4 abuf[8];

    const uint4* A1 = a_ptr(g_W1p, warp, lane);
    const uint4* A2 = a_ptr(g_W2p, warp, lane);

    // ---- reducer persistent state (threads 0..31: row rw, batch b) ----
    const int red_r  = tid >> 1;           // 0..15
    const int red_b  = tid & 1;
    const int red_rw = blockIdx.x * ROWS_PB + red_r;
    float hbase = 0.f, ksumr = 0.f, bias1 = 0.f, bias2 = 0.f;
    if (tid < 32) {
        hbase = (red_b ? h_b : h_f)[red_rw];
        bias1 = f_b1[red_rw];
        bias2 = f_b2[red_rw];
        __stcg(reinterpret_cast<unsigned short*>(&g_vh[red_b * NH + red_rw]),
               __half_as_ushort(__float2half(hbase)));
    }

    // ---- GRU x-half dot (independent of ODE): 8 warps x 2 rows ----
    for (int j = tid; j < NH; j += TPB) { sm.svf[0][j] = x_f[j]; sm.svf[1][j] = x_b[j]; }
    __syncthreads();
    #pragma unroll
    for (int r2 = 0; r2 < 2; r2++) {
        const int row = blockIdx.x * ROWS_PB + warp * 2 + r2;
        float a0, a1;
        wdot_f2<NH/4>(reinterpret_cast<const float4*>(i2h_W + (size_t)row * K2),
                      reinterpret_cast<const float4*>(sm.svf[0]),
                      reinterpret_cast<const float4*>(sm.svf[1]), lane, a0, a1);
        if (lane == 0) { g_xd[0][row] = a0; g_xd[1][row] = a1; }
    }
    a_prefetch(abuf, A1);
    bar_arrive();

    // ---- RK4 ODE: 120 phases ----
    for (int s = 0; s < nsteps; s++) {
        for (int stage = 0; stage < 4; stage++) {
            // ======== layer 1: u = tanh(W1 @ v + b1) ========
            bar_wait(target);
            {   // 16 KB .cg copy: g_vh -> smem (4 uint4 per thread)
                const uint4* src = reinterpret_cast<const uint4*>(&g_vh[0]);
                uint4* dst = reinterpret_cast<uint4*>(svh);
                #pragma unroll
                for (int r = 0; r < 4; r++)
                    dst[tid + r * TPB] = __ldcg(src + tid + r * TPB);
            }
            __syncthreads();
            ode_mma(abuf, A1, svh, sm.part, warp, lane);
            __syncthreads();
            a_prefetch(abuf, A2);          // next matvec's A streams during reduce
            if (tid < 32) {
                float acc = 0.f;
                #pragma unroll
                for (int kc = 0; kc < 8; kc++) acc += sm.part[(kc * 16 + red_r) * 2 + red_b];
                const float u = tanhf(acc + bias1);
                __stcg(reinterpret_cast<unsigned short*>(&g_uh[red_b * NH + red_rw]),
                       __half_as_ushort(__float2half(u)));
            }
            bar_arrive();

            // ======== layer 2: k = W2 @ u + b2; RK4 state update ========
            bar_wait(target);
            {   // 16 KB .cg copy: g_uh -> smem
                const uint4* src = reinterpret_cast<const uint4*>(&g_uh[0]);
                uint4* dst = reinterpret_cast<uint4*>(svh);
                #pragma unroll
                for (int r = 0; r < 4; r++)
                    dst[tid + r * TPB] = __ldcg(src + tid + r * TPB);
            }
            __syncthreads();
            ode_mma(abuf, A2, svh, sm.part, warp, lane);
            __syncthreads();
            a_prefetch(abuf, A1);
            if (tid < 32) {
                float acc = 0.f;
                #pragma unroll
                for (int kc = 0; kc < 8; kc++) acc += sm.part[(kc * 16 + red_r) * 2 + red_b];
                const float kv = acc + bias2;
                const float* t = red_b ? tb : tf;
                const float dt = t[s+1] - t[s];
                float vnext;
                if (stage == 0)      { ksumr = kv;           vnext = hbase + 0.5f*dt*kv; }
                else if (stage == 1) { ksumr += 2.f*kv;      vnext = hbase + 0.5f*dt*kv; }
                else if (stage == 2) { ksumr += 2.f*kv;      vnext = hbase + dt*kv; }
                else {
                    ksumr += kv;
                    hbase += (dt * (1.0f/6.0f)) * ksumr;
                    vnext = hbase;
                    if (s == nsteps - 1)
                        __stcg(&g_vfin[red_b][red_rw], hbase);
                }
                __stcg(reinterpret_cast<unsigned short*>(&g_vh[red_b * NH + red_rw]),
                       __half_as_ushort(__float2half(vnext)));
            }
            bar_arrive();
        }
    }

    // ---- GRU phase 0: g = sigmoid(xd + W_h @ h_fin + b) ----
    bar_wait(target);
    {
        const float4* src = reinterpret_cast<const float4*>(&g_vfin[0][0]);
        float4* dst = reinterpret_cast<float4*>(&sm.svf[0][0]);
        #pragma unroll
        for (int r = 0; r < 8; r++) dst[tid + r * TPB] = __ldcg(src + tid + r * TPB);
    }
    __syncthreads();
    #pragma unroll
    for (int r2 = 0; r2 < 2; r2++) {
        const int row = blockIdx.x * ROWS_PB + warp * 2 + r2;
        float a0, a1;
        wdot_f2<NH/4>(reinterpret_cast<const float4*>(i2h_W + (size_t)row * K2 + NH),
                      reinterpret_cast<const float4*>(sm.svf[0]),
                      reinterpret_cast<const float4*>(sm.svf[1]), lane, a0, a1);
        if (lane == 0) {
            const float bb = i2h_b[row];
            __stcg(&g_g[0][row], 1.f / (1.f + expf(-(g_xd[0][row] + a0 + bb))));
            __stcg(&g_g[1][row], 1.f / (1.f + expf(-(g_xd[1][row] + a1 + bb))));
        }
    }
    bar_arrive();

    // ---- GRU phase 1: h_hat = tanh(xd + W_h @ (g .* h_fin) + b) ----
    bar_wait(target);
    #pragma unroll
    for (int b = 0; b < 2; b++)
        for (int j = tid; j < NH; j += TPB)
            sm.svf[b][j] = __ldcg(&g_g[b][j]) * __ldcg(&g_vfin[b][j]);
    __syncthreads();
    #pragma unroll
    for (int r2 = 0; r2 < 2; r2++) {
        const int row = blockIdx.x * ROWS_PB + warp * 2 + r2;
        float a0, a1;
        wdot_f2<NH/4>(reinterpret_cast<const float4*>(i2h_W + (size_t)row * K2 + NH),
                      reinterpret_cast<const float4*>(sm.svf[0]),
                      reinterpret_cast<const float4*>(sm.svf[1]), lane, a0, a1);
        if (lane == 0) {
            const float bb = i2h_b[row];
            __stcg(&g_hhat[0][row], tanhf(g_xd[0][row] + a0 + bb));
            __stcg(&g_hhat[1][row], tanhf(g_xd[1][row] + a1 + bb));
        }
    }
    bar_arrive();

    // ---- GRU blend + emit h_f / h_b ----
    bar_wait(target);
    {
        int i = blockIdx.x * (2 * NH / GRIDB) + tid;   // 32 elems per block
        if (tid < 2 * NH / GRIDB) {
            const int b = i >> 12, j = i & (NH - 1);
            const float g  = __ldcg(&g_g[b][j]);
            const float hn = g * __ldcg(&g_vfin[b][j]) + (1.f - g) * __ldcg(&g_hhat[b][j]);
            __stcg(&g_hnew[b][j], hn);
            out[NH + i] = hn;
        }
    }
    bar_arrive();

    // ---- output matvec ----
    bar_wait(target);
    {
        const float4* src = reinterpret_cast<const float4*>(&g_hnew[0][0]);
        float4* dst = reinterpret_cast<float4*>(&sm.svf[0][0]);
        #pragma unroll
        for (int r = 0; r < 8; r++) dst[tid + r * TPB] = __ldcg(src + tid + r * TPB);
    }
    __syncthreads();
    #pragma unroll
    for (int r2 = 0; r2 < 2; r2++) {
        const int row = blockIdx.x * ROWS_PB + warp * 2 + r2;
        float a = wdot_f1<K2/4>(reinterpret_cast<const float4*>(h2o_W + (size_t)row * K2),
                                reinterpret_cast<const float4*>(&sm.svf[0][0]), lane);
        if (lane == 0) out[row] = a + h2o_b[row];
    }
}

extern "C" void kernel_launch(void* const* d_in, const int* in_sizes, int n_in,
                              void* d_out, int out_size)
{
    const float* x_f   = (const float*)d_in[0];
    const float* x_b   = (const float*)d_in[1];
    const float* h_f   = (const float*)d_in[2];
    const float* h_b   = (const float*)d_in[3];
    const float* t_f   = (const float*)d_in[4];
    const float* t_b   = (const float*)d_in[5];
    const float* i2h_W = (const float*)d_in[6];
    const float* i2h_b = (const float*)d_in[7];
    const float* h2o_W = (const float*)d_in[8];
    const float* h2o_b = (const float*)d_in[9];
    const float* f_W1  = (const float*)d_in[10];
    const float* f_b1  = (const float*)d_in[11];
    const float* f_W2  = (const float*)d_in[12];
    const float* f_b2  = (const float*)d_in[13];
    float* out = (float*)d_out;

    const int T = in_sizes[4];
    const int nsteps = T - 1;

    __half *w1p, *w2p;
    cudaGetSymbolAddress((void**)&w1p, g_W1p);
    cudaGetSymbolAddress((void**)&w2p, g_W2p);

    const int permBlocks = (NH / 16) * (NH / 16) * 32 / 256;   // 8192
    k_perm<<<permBlocks, 256>>>(f_W1, w1p);
    k_perm<<<permBlocks, 256>>>(f_W2, w2p);
    k_reset<<<1, 1>>>();

    k_all<<<GRIDB, TPB>>>(f_b1, f_b2, i2h_W, i2h_b, h2o_W, h2o_b,
                          x_f, x_b, h_f, h_b, t_f, t_b, out, nsteps);
}

// round 16
// speedup vs baseline: 1.6065x; 1.0129x over previous
#include <cuda_runtime.h>
#include <cuda_fp16.h>
#include <math.h>
#include <stdint.h>

#define NH     4096
#define K2     8192
#define GRIDB  128          // blocks (<= 148 SMs -> co-resident, barrier safe)
#define TPB    512          // 16 warps
#define ROWS_PB 32

// ---------------- persistent device scratch (no allocations) ----------------
__device__ __half g_W1p[(size_t)NH * NH];   // fp16 f_W1, fragment-major
__device__ __half g_W2p[(size_t)NH * NH];   // fp16 f_W2, fragment-major
__device__ __half g_vh[2 * NH];             // current ODE input vector v (fp16)
__device__ __half g_uh[2 * NH];             // tanh hidden u (fp16)
__device__ float  g_vfin[2][NH];            // h after full integration (fp32)
__device__ float  g_g[2][NH];
__device__ float  g_hhat[2][NH];
__device__ float  g_hnew[2][NH];
__device__ float  g_xd[2][NH];
__device__ unsigned g_arrive;

__global__ void k_reset() { g_arrive = 0u; }

// ---------------- full-grid barrier: release-red / acquire-poll -------------
__device__ __forceinline__ void bar_arrive()
{
    __syncthreads();
    if (threadIdx.x == 0) {
        unsigned* p = &g_arrive;
        asm volatile("red.release.gpu.global.add.u32 [%0], 1;" :: "l"(p) : "memory");
    }
}
__device__ __forceinline__ void bar_wait(unsigned& target)
{
    if (threadIdx.x == 0) {
        unsigned* p = &g_arrive;
        unsigned v;
        do {
            asm volatile("ld.acquire.gpu.global.u32 %0, [%1];" : "=r"(v) : "l"(p) : "memory");
        } while (v < target);
    }
    __syncthreads();
    target += GRIDB;
}

// ---------------- fast tanh (accuracy-verified in R12/R13) ------------------
__device__ __forceinline__ float tanh_fast(float x)
{
    float y;
    asm("tanh.approx.f32 %0, %1;" : "=f"(y) : "f"(x));
    return y;
}

// ---------------- HMMA m16n8k16 fp32-accum ----------------
__device__ __forceinline__ void mma16816(float c[4], const uint4& a,
                                         uint32_t b0, uint32_t b1)
{
    asm volatile(
        "mma.sync.aligned.m16n8k16.row.col.f32.f16.f16.f32 "
        "{%0,%1,%2,%3}, {%4,%5,%6,%7}, {%8,%9}, {%0,%1,%2,%3};"
        : "+f"(c[0]), "+f"(c[1]), "+f"(c[2]), "+f"(c[3])
        : "r"(a.x), "r"(a.y), "r"(a.z), "r"(a.w), "r"(b0), "r"(b1));
}

__device__ __forceinline__ const uint4* a_ptr(const __half* Wp, int warp, int lane)
{
    const int rg = warp >> 3, kc = warp & 7;
    const int rg_glob = blockIdx.x * 2 + rg;
    return reinterpret_cast<const uint4*>(Wp)
         + ((size_t)rg_glob * 256 + kc * 32) * 32 + lane;
}

__device__ __forceinline__ void a_prefetch(uint4* abuf, const uint4* A)
{
    #pragma unroll
    for (int p = 0; p < 8; p++) abuf[p] = A[p * 32];
}

// ---- fused per-block weight permutation: fp32 W rows -> fp16 A-fragments ---
// Block handles only its own 32 rows (2 rg x 256 kt tiles) of each matrix.
// These are the only fragments this block's a_ptr ever reads.
__device__ __forceinline__ void perm_slice(const float* __restrict__ W,
                                           __half* __restrict__ P, int tid)
{
    // 2 rg_loc x 256 kt x 32 lanes = 16384 items
    for (int i = tid; i < 2 * 256 * 32; i += TPB) {
        const int lane   = i & 31;
        const int kt     = (i >> 5) & 255;
        const int rg_loc = i >> 13;
        const int rg     = blockIdx.x * 2 + rg_loc;
        const int R0 = rg * 16, C0 = kt * 16;
        const int g = lane >> 2, q = lane & 3;
        const float2* r0p = reinterpret_cast<const float2*>(W + (size_t)(R0 + g)     * NH + C0 + 2*q);
        const float2* r8p = reinterpret_cast<const float2*>(W + (size_t)(R0 + 8 + g) * NH + C0 + 2*q);
        float2 a01 = r0p[0];
        float2 a23 = r8p[0];
        float2 a45 = r0p[4];
        float2 a67 = r8p[4];
        __half2 h0 = __floats2half2_rn(a01.x, a01.y);
        __half2 h1 = __floats2half2_rn(a23.x, a23.y);
        __half2 h2 = __floats2half2_rn(a45.x, a45.y);
        __half2 h3 = __floats2half2_rn(a67.x, a67.y);
        uint4 o;
        o.x = *reinterpret_cast<uint32_t*>(&h0);
        o.y = *reinterpret_cast<uint32_t*>(&h1);
        o.z = *reinterpret_cast<uint32_t*>(&h2);
        o.w = *reinterpret_cast<uint32_t*>(&h3);
        reinterpret_cast<uint4*>(P)[(size_t)(rg * 256 + kt) * 32 + lane] = o;
    }
}

// mma mainloop: ring 8, 2 accumulator chains, 32 steps (K=512 per warp)
__device__ __forceinline__ void ode_mma(uint4* abuf, const uint4* A,
                                        const __half* __restrict__ svh,   // [2][NH] flat
                                        float* __restrict__ part,
                                        int warp, int lane)
{
    const int rg = warp >> 3, kc = warp & 7;
    const int n = lane >> 2, q = lane & 3;
    const bool hasB = (n < 2);
    const __half* vb = svh + (hasB ? n : 0) * NH + kc * 512 + q * 2;

    float c0[4] = {0.f,0.f,0.f,0.f}, c1[4] = {0.f,0.f,0.f,0.f};
    #pragma unroll
    for (int s = 0; s < 32; s++) {
        uint4 a = abuf[s & 7];
        if (s < 24) abuf[s & 7] = A[(size_t)(s + 8) * 32];
        uint32_t b0 = 0u, b1 = 0u;
        if (hasB) {
            b0 = *reinterpret_cast<const uint32_t*>(vb + s * 16);
            b1 = *reinterpret_cast<const uint32_t*>(vb + s * 16 + 8);
        }
        if (s & 1) mma16816(c1, a, b0, b1);
        else       mma16816(c0, a, b0, b1);
    }
    if (q == 0) {
        const int r = rg * 16 + n;
        part[(kc * 32 + r)     * 2 + 0] = c0[0] + c1[0];
        part[(kc * 32 + r)     * 2 + 1] = c0[1] + c1[1];
        part[(kc * 32 + r + 8) * 2 + 0] = c0[2] + c1[2];
        part[(kc * 32 + r + 8) * 2 + 1] = c0[3] + c1[3];
    }
}

// ---------------- fp32 warp dots (GRU / out) ----------------
template<int K4>
__device__ __forceinline__ void wdot_f2(const float4* __restrict__ Wr,
                                        const float4* __restrict__ v0,
                                        const float4* __restrict__ v1,
                                        int lane, float& a0, float& a1)
{
    a0 = 0.f; a1 = 0.f;
    #pragma unroll 8
    for (int i = lane; i < K4; i += 32) {
        float4 w = Wr[i], x0 = v0[i], x1 = v1[i];
        a0 += w.x*x0.x + w.y*x0.y + w.z*x0.z + w.w*x0.w;
        a1 += w.x*x1.x + w.y*x1.y + w.z*x1.z + w.w*x1.w;
    }
    #pragma unroll
    for (int off = 16; off; off >>= 1) {
        a0 += __shfl_down_sync(0xffffffffu, a0, off);
        a1 += __shfl_down_sync(0xffffffffu, a1, off);
    }
}

template<int K4>
__device__ __forceinline__ float wdot_f1(const float4* __restrict__ Wr,
                                         const float4* __restrict__ v, int lane)
{
    float a = 0.f;
    #pragma unroll 8
    for (int i = lane; i < K4; i += 32) {
        float4 w = Wr[i], x = v[i];
        a += w.x*x.x + w.y*x.y + w.z*x.z + w.w*x.w;
    }
    #pragma unroll
    for (int off = 16; off; off >>= 1) a += __shfl_down_sync(0xffffffffu, a, off);
    return a;
}

// ---------------- the whole model in one persistent kernel ------------------
__global__ __launch_bounds__(TPB, 1)
void k_all(const float* __restrict__ f_W1, const float* __restrict__ f_W2,
           const float* __restrict__ f_b1, const float* __restrict__ f_b2,
           const float* __restrict__ i2h_W, const float* __restrict__ i2h_b,
           const float* __restrict__ h2o_W, const float* __restrict__ h2o_b,
           const float* __restrict__ x_f, const float* __restrict__ x_b,
           const float* __restrict__ h_f, const float* __restrict__ h_b,
           const float* __restrict__ tf, const float* __restrict__ tb,
           float* __restrict__ out, int nsteps)
{
    __shared__ __half svh[2 * NH];         // 16 KB (ODE v / u staging)
    __shared__ union {
        float svf[2][NH];                  // 32 KB (GRU / out)
        float part[8 * 32 * 2];            //  2 KB (ODE partials)
    } sm;

    const int tid  = threadIdx.x;
    const int warp = tid >> 5, lane = tid & 31;
    unsigned target = GRIDB;
    uint4 abuf[8];

    const uint4* A1 = a_ptr(g_W1p, warp, lane);
    const uint4* A2 = a_ptr(g_W2p, warp, lane);

    // ---- reducer persistent state (threads 0..63: row rw, batch b) ----
    const int red_r  = tid >> 1;
    const int red_b  = tid & 1;
    const int red_rw = blockIdx.x * ROWS_PB + red_r;
    float hbase = 0.f, ksumr = 0.f, bias1 = 0.f, bias2 = 0.f;
    if (tid < 64) {
        hbase = (red_b ? h_b : h_f)[red_rw];
        bias1 = f_b1[red_rw];
        bias2 = f_b2[red_rw];
        __stcg(reinterpret_cast<unsigned short*>(&g_vh[red_b * NH + red_rw]),
               __half_as_ushort(__float2half(hbase)));
    }

    // ---- fused weight permutation: this block's own 32-row slices ----
    perm_slice(f_W1, g_W1p, tid);
    perm_slice(f_W2, g_W2p, tid);

    // ---- GRU x-half dot (independent of ODE) ----
    for (int j = tid; j < NH; j += TPB) { sm.svf[0][j] = x_f[j]; sm.svf[1][j] = x_b[j]; }
    __syncthreads();   // orders perm stores + svf fills before all later reads
    #pragma unroll
    for (int r2 = 0; r2 < 2; r2++) {
        const int row = blockIdx.x * ROWS_PB + warp * 2 + r2;
        float a0, a1;
        wdot_f2<NH/4>(reinterpret_cast<const float4*>(i2h_W + (size_t)row * K2),
                      reinterpret_cast<const float4*>(sm.svf[0]),
                      reinterpret_cast<const float4*>(sm.svf[1]), lane, a0, a1);
        if (lane == 0) { g_xd[0][row] = a0; g_xd[1][row] = a1; }
    }
    a_prefetch(abuf, A1);
    bar_arrive();

    // ---- RK4 ODE: 120 phases ----
    for (int s = 0; s < nsteps; s++) {
        for (int stage = 0; stage < 4; stage++) {
            // ======== layer 1: u = tanh(W1 @ v + b1) ========
            bar_wait(target);
            {   // 16 KB .cg copy: g_vh -> smem
                const uint4* src = reinterpret_cast<const uint4*>(&g_vh[0]);
                uint4* dst = reinterpret_cast<uint4*>(svh);
                dst[tid]       = __ldcg(src + tid);
                dst[tid + TPB] = __ldcg(src + tid + TPB);
            }
            __syncthreads();
            ode_mma(abuf, A1, svh, sm.part, warp, lane);
            __syncthreads();
            a_prefetch(abuf, A2);          // streams during reduce + barrier
            if (tid < 64) {
                float acc = 0.f;
                #pragma unroll
                for (int kc = 0; kc < 8; kc++) acc += sm.part[(kc * 32 + red_r) * 2 + red_b];
                const float u = tanh_fast(acc + bias1);
                __stcg(reinterpret_cast<unsigned short*>(&g_uh[red_b * NH + red_rw]),
                       __half_as_ushort(__float2half(u)));
            }
            bar_arrive();

            // ======== layer 2: k = W2 @ u + b2; RK4 state update ========
            bar_wait(target);
            {   // 16 KB .cg copy: g_uh -> smem
                const uint4* src = reinterpret_cast<const uint4*>(&g_uh[0]);
                uint4* dst = reinterpret_cast<uint4*>(svh);
                dst[tid]       = __ldcg(src + tid);
                dst[tid + TPB] = __ldcg(src + tid + TPB);
            }
            __syncthreads();
            ode_mma(abuf, A2, svh, sm.part, warp, lane);
            __syncthreads();
            a_prefetch(abuf, A1);
            if (tid < 64) {
                float acc = 0.f;
                #pragma unroll
                for (int kc = 0; kc < 8; kc++) acc += sm.part[(kc * 32 + red_r) * 2 + red_b];
                const float kv = acc + bias2;
                const float* t = red_b ? tb : tf;
                const float dt = t[s+1] - t[s];
                float vnext;
                if (stage == 0)      { ksumr = kv;           vnext = hbase + 0.5f*dt*kv; }
                else if (stage == 1) { ksumr += 2.f*kv;      vnext = hbase + 0.5f*dt*kv; }
                else if (stage == 2) { ksumr += 2.f*kv;      vnext = hbase + dt*kv; }
                else {
                    ksumr += kv;
                    hbase += (dt * (1.0f/6.0f)) * ksumr;
                    vnext = hbase;
                    if (s == nsteps - 1)
                        __stcg(&g_vfin[red_b][red_rw], hbase);
                }
                __stcg(reinterpret_cast<unsigned short*>(&g_vh[red_b * NH + red_rw]),
                       __half_as_ushort(__float2half(vnext)));
            }
            bar_arrive();
        }
    }

    // ---- GRU phase 0: g = sigmoid(xd + W_h @ h_fin + b) ----
    bar_wait(target);
    {
        const float4* src = reinterpret_cast<const float4*>(&g_vfin[0][0]);
        float4* dst = reinterpret_cast<float4*>(&sm.svf[0][0]);
        #pragma unroll
        for (int r = 0; r < 4; r++) dst[tid + r * TPB] = __ldcg(src + tid + r * TPB);
    }
    __syncthreads();
    #pragma unroll
    for (int r2 = 0; r2 < 2; r2++) {
        const int row = blockIdx.x * ROWS_PB + warp * 2 + r2;
        float a0, a1;
        wdot_f2<NH/4>(reinterpret_cast<const float4*>(i2h_W + (size_t)row * K2 + NH),
                      reinterpret_cast<const float4*>(sm.svf[0]),
                      reinterpret_cast<const float4*>(sm.svf[1]), lane, a0, a1);
        if (lane == 0) {
            const float bb = i2h_b[row];
            __stcg(&g_g[0][row], 1.f / (1.f + expf(-(g_xd[0][row] + a0 + bb))));
            __stcg(&g_g[1][row], 1.f / (1.f + expf(-(g_xd[1][row] + a1 + bb))));
        }
    }
    bar_arrive();

    // ---- GRU phase 1: h_hat = tanh(xd + W_h @ (g .* h_fin) + b) ----
    bar_wait(target);
    #pragma unroll
    for (int b = 0; b < 2; b++)
        for (int j = tid; j < NH; j += TPB)
            sm.svf[b][j] = __ldcg(&g_g[b][j]) * __ldcg(&g_vfin[b][j]);
    __syncthreads();
    #pragma unroll
    for (int r2 = 0; r2 < 2; r2++) {
        const int row = blockIdx.x * ROWS_PB + warp * 2 + r2;
        float a0, a1;
        wdot_f2<NH/4>(reinterpret_cast<const float4*>(i2h_W + (size_t)row * K2 + NH),
                      reinterpret_cast<const float4*>(sm.svf[0]),
                      reinterpret_cast<const float4*>(sm.svf[1]), lane, a0, a1);
        if (lane == 0) {
            const float bb = i2h_b[row];
            __stcg(&g_hhat[0][row], tanhf(g_xd[0][row] + a0 + bb));
            __stcg(&g_hhat[1][row], tanhf(g_xd[1][row] + a1 + bb));
        }
    }
    bar_arrive();

    // ---- GRU blend + emit h_f / h_b ----
    bar_wait(target);
    {
        int i = blockIdx.x * TPB + tid;
        if (i < 2 * NH) {
            const int b = i >> 12, j = i & (NH - 1);
            const float g  = __ldcg(&g_g[b][j]);
            const float hn = g * __ldcg(&g_vfin[b][j]) + (1.f - g) * __ldcg(&g_hhat[b][j]);
            __stcg(&g_hnew[b][j], hn);
            out[NH + i] = hn;
        }
    }
    bar_arrive();

    // ---- output matvec ----
    bar_wait(target);
    {
        const float4* src = reinterpret_cast<const float4*>(&g_hnew[0][0]);
        float4* dst = reinterpret_cast<float4*>(&sm.svf[0][0]);
        #pragma unroll
        for (int r = 0; r < 4; r++) dst[tid + r * TPB] = __ldcg(src + tid + r * TPB);
    }
    __syncthreads();
    #pragma unroll
    for (int r2 = 0; r2 < 2; r2++) {
        const int row = blockIdx.x * ROWS_PB + warp * 2 + r2;
        float a = wdot_f1<K2/4>(reinterpret_cast<const float4*>(h2o_W + (size_t)row * K2),
                                reinterpret_cast<const float4*>(&sm.svf[0][0]), lane);
        if (lane == 0) out[row] = a + h2o_b[row];
    }
}

extern "C" void kernel_launch(void* const* d_in, const int* in_sizes, int n_in,
                              void* d_out, int out_size)
{
    const float* x_f   = (const float*)d_in[0];
    const float* x_b   = (const float*)d_in[1];
    const float* h_f   = (const float*)d_in[2];
    const float* h_b   = (const float*)d_in[3];
    const float* t_f   = (const float*)d_in[4];
    const float* t_b   = (const float*)d_in[5];
    const float* i2h_W = (const float*)d_in[6];
    const float* i2h_b = (const float*)d_in[7];
    const float* h2o_W = (const float*)d_in[8];
    const float* h2o_b = (const float*)d_in[9];
    const float* f_W1  = (const float*)d_in[10];
    const float* f_b1  = (const float*)d_in[11];
    const float* f_W2  = (const float*)d_in[12];
    const float* f_b2  = (const float*)d_in[13];
    float* out = (float*)d_out;

    const int T = in_sizes[4];
    const int nsteps = T - 1;

    k_reset<<<1, 1>>>();
    k_all<<<GRIDB, TPB>>>(f_W1, f_W2, f_b1, f_b2, i2h_W, i2h_b, h2o_W, h2o_b,
                          x_f, x_b, h_f, h_b, t_f, t_b, out, nsteps);
}